// round 2
// baseline (speedup 1.0000x reference)
#include <cuda_runtime.h>
#include <cuda_bf16.h>
#include <stdint.h>

#define NUM_USERS 100000
#define NUM_ITEMS 50000
#define N_NODES   (NUM_USERS + NUM_ITEMS)   // 150000
#define EMBED_DIM 64
#define NUM_LAYERS 3
#define N_EDGES   1000000

#define SCAN_BS   1024
#define N_SCAN_BLOCKS ((N_NODES + SCAN_BS - 1) / SCAN_BS)   // 147

// ---- static device scratch (no allocation allowed) ----
__device__ int   g_deg[N_NODES];
__device__ float g_dinv[N_NODES];
__device__ int   g_off[N_NODES + 1];
__device__ int   g_cur[N_NODES];
__device__ int   g_bsum[N_SCAN_BLOCKS];
__device__ int   g_csr_src[N_EDGES];
__device__ float g_csr_norm[N_EDGES];
__device__ float g_x0[N_NODES * EMBED_DIM];
__device__ float g_x1[N_NODES * EMBED_DIM];

// -------------------- setup kernels --------------------

__global__ void k_init_counts() {
    int i = blockIdx.x * blockDim.x + threadIdx.x;
    if (i < N_NODES) { g_deg[i] = 0; g_cur[i] = 0; }
}

__global__ void k_degree(const int* __restrict__ edge_index) {
    int e = blockIdx.x * blockDim.x + threadIdx.x;
    if (e < N_EDGES) {
        int dst = edge_index[N_EDGES + e];
        atomicAdd(&g_deg[dst], 1);
    }
}

__global__ void k_dinv() {
    int i = blockIdx.x * blockDim.x + threadIdx.x;
    if (i < N_NODES) {
        int d = g_deg[i];
        g_dinv[i] = (d > 0) ? rsqrtf((float)d) : 0.0f;
    }
}

// exclusive scan, stage 1: per-block (Hillis-Steele inclusive, then -v)
__global__ void k_scan_blocks() {
    __shared__ int s[SCAN_BS];
    int tid = threadIdx.x;
    int i = blockIdx.x * SCAN_BS + tid;
    int v = (i < N_NODES) ? g_deg[i] : 0;
    s[tid] = v;
    __syncthreads();
    #pragma unroll
    for (int d = 1; d < SCAN_BS; d <<= 1) {
        int t = (tid >= d) ? s[tid - d] : 0;
        __syncthreads();
        s[tid] += t;
        __syncthreads();
    }
    if (i < N_NODES) g_off[i] = s[tid] - v;   // exclusive
    if (tid == SCAN_BS - 1) g_bsum[blockIdx.x] = s[tid];
}

// stage 2: tiny serial scan of 147 block sums (negligible cost)
__global__ void k_scan_aux() {
    if (threadIdx.x == 0 && blockIdx.x == 0) {
        int run = 0;
        for (int i = 0; i < N_SCAN_BLOCKS; i++) {
            int v = g_bsum[i];
            g_bsum[i] = run;
            run += v;
        }
    }
}

// stage 3: add block offsets
__global__ void k_scan_add() {
    int i = blockIdx.x * blockDim.x + threadIdx.x;
    if (i < N_NODES) g_off[i] += g_bsum[i >> 10];
    if (i == 0) g_off[N_NODES] = N_EDGES;
}

// scatter edges into CSR-by-dst, precompute norm = dinv[src]*dinv[dst]
__global__ void k_scatter(const int* __restrict__ edge_index) {
    int e = blockIdx.x * blockDim.x + threadIdx.x;
    if (e < N_EDGES) {
        int src = edge_index[e];
        int dst = edge_index[N_EDGES + e];
        int pos = g_off[dst] + atomicAdd(&g_cur[dst], 1);
        g_csr_src[pos]  = src;
        g_csr_norm[pos] = g_dinv[src] * g_dinv[dst];
    }
}

// init: x0 = emb ; acc(d_out) = 0.25 * emb   (fold the /(L+1) scaling in)
__global__ void k_init_emb(const float4* __restrict__ emb, float4* __restrict__ out) {
    int i = blockIdx.x * blockDim.x + threadIdx.x;
    if (i < N_NODES * EMBED_DIM / 4) {
        float4 v = emb[i];
        ((float4*)g_x0)[i] = v;
        float4 a;
        a.x = 0.25f * v.x; a.y = 0.25f * v.y;
        a.z = 0.25f * v.z; a.w = 0.25f * v.w;
        out[i] = a;
    }
}

// -------------------- propagation layer --------------------
// one warp per node, float2 per lane (32 lanes x 2 = 64 dims)
__global__ void __launch_bounds__(256) k_prop(int flip, float* __restrict__ out_acc) {
    const float2* __restrict__ xin  = (const float2*)(flip ? g_x1 : g_x0);
    float2*       __restrict__ xout = (float2*)      (flip ? g_x0 : g_x1);

    int gtid = blockIdx.x * blockDim.x + threadIdx.x;
    int node = gtid >> 5;
    int lane = gtid & 31;
    if (node >= N_NODES) return;

    int beg = g_off[node];
    int end = g_off[node + 1];

    float2 sum = make_float2(0.0f, 0.0f);
    for (int e = beg; e < end; e++) {
        int   s = g_csr_src[e];     // warp-broadcast load
        float w = g_csr_norm[e];    // warp-broadcast load
        float2 v = xin[(size_t)s * 32 + lane];
        sum.x = fmaf(v.x, w, sum.x);
        sum.y = fmaf(v.y, w, sum.y);
    }

    size_t oi = (size_t)node * 32 + lane;
    xout[oi] = sum;

    float2* acc = (float2*)out_acc;
    float2 a = acc[oi];
    a.x = fmaf(0.25f, sum.x, a.x);
    a.y = fmaf(0.25f, sum.y, a.y);
    acc[oi] = a;
}

// -------------------- launch --------------------

extern "C" void kernel_launch(void* const* d_in, const int* in_sizes, int n_in,
                              void* d_out, int out_size) {
    const int*   edge_index = (const int*)d_in[0];     // int32 (JAX x64 disabled)
    const float* emb_weight = (const float*)d_in[1];
    float*       out        = (float*)d_out;

    const int BS = 256;
    int gn = (N_NODES + BS - 1) / BS;
    int ge = (N_EDGES + BS - 1) / BS;

    k_init_counts<<<gn, BS>>>();
    k_degree<<<ge, BS>>>(edge_index);
    k_dinv<<<gn, BS>>>();
    k_scan_blocks<<<N_SCAN_BLOCKS, SCAN_BS>>>();
    k_scan_aux<<<1, 32>>>();
    k_scan_add<<<gn, BS>>>();
    k_scatter<<<ge, BS>>>(edge_index);

    int gv = (N_NODES * EMBED_DIM / 4 + BS - 1) / BS;
    k_init_emb<<<gv, BS>>>((const float4*)emb_weight, (float4*)out);

    int gp = (N_NODES * 32 + BS - 1) / BS;
    k_prop<<<gp, BS>>>(0, out);   // reads g_x0 -> writes g_x1
    k_prop<<<gp, BS>>>(1, out);   // reads g_x1 -> writes g_x0
    k_prop<<<gp, BS>>>(0, out);   // reads g_x0 -> writes g_x1
}

// round 4
// speedup vs baseline: 1.2807x; 1.2807x over previous
#include <cuda_runtime.h>
#include <cuda_bf16.h>
#include <stdint.h>

#define NUM_USERS 100000
#define NUM_ITEMS 50000
#define N_NODES   (NUM_USERS + NUM_ITEMS)   // 150000
#define EMBED_DIM 64
#define NUM_LAYERS 3
#define N_EDGES   1000000

#define SCAN_BS   1024
#define N_SCAN_BLOCKS ((N_NODES + SCAN_BS - 1) / SCAN_BS)   // 147

// ---- static device scratch (no allocation allowed) ----
__device__ int   g_deg[N_NODES];
__device__ float g_dinv[N_NODES];
__device__ int   g_off[N_NODES + 1];
__device__ int   g_cur[N_NODES];
__device__ int   g_bsum[N_SCAN_BLOCKS];
__device__ int2  g_csr[N_EDGES];            // {src, norm_bits} packed
__device__ float g_x1[N_NODES * EMBED_DIM];
__device__ float g_x2[N_NODES * EMBED_DIM];

// -------------------- setup kernels --------------------

__global__ void k_init_counts() {
    int i = blockIdx.x * blockDim.x + threadIdx.x;
    if (i < N_NODES) { g_deg[i] = 0; g_cur[i] = 0; }
}

__global__ void k_degree(const int* __restrict__ edge_index) {
    int e = blockIdx.x * blockDim.x + threadIdx.x;
    if (e < N_EDGES) {
        int dst = edge_index[N_EDGES + e];
        atomicAdd(&g_deg[dst], 1);
    }
}

__global__ void k_dinv() {
    int i = blockIdx.x * blockDim.x + threadIdx.x;
    if (i < N_NODES) {
        int d = g_deg[i];
        g_dinv[i] = (d > 0) ? rsqrtf((float)d) : 0.0f;
    }
}

// exclusive scan, stage 1: per-block (Hillis-Steele inclusive, then -v)
__global__ void k_scan_blocks() {
    __shared__ int s[SCAN_BS];
    int tid = threadIdx.x;
    int i = blockIdx.x * SCAN_BS + tid;
    int v = (i < N_NODES) ? g_deg[i] : 0;
    s[tid] = v;
    __syncthreads();
    #pragma unroll
    for (int d = 1; d < SCAN_BS; d <<= 1) {
        int t = (tid >= d) ? s[tid - d] : 0;
        __syncthreads();
        s[tid] += t;
        __syncthreads();
    }
    if (i < N_NODES) g_off[i] = s[tid] - v;   // exclusive
    if (tid == SCAN_BS - 1) g_bsum[blockIdx.x] = s[tid];
}

__global__ void k_scan_aux() {
    if (threadIdx.x == 0 && blockIdx.x == 0) {
        int run = 0;
        for (int i = 0; i < N_SCAN_BLOCKS; i++) {
            int v = g_bsum[i];
            g_bsum[i] = run;
            run += v;
        }
    }
}

__global__ void k_scan_add() {
    int i = blockIdx.x * blockDim.x + threadIdx.x;
    if (i < N_NODES) g_off[i] += g_bsum[i >> 10];
    if (i == 0) g_off[N_NODES] = N_EDGES;
}

// scatter edges into CSR-by-dst, packed {src, norm}
__global__ void k_scatter(const int* __restrict__ edge_index) {
    int e = blockIdx.x * blockDim.x + threadIdx.x;
    if (e < N_EDGES) {
        int src = edge_index[e];
        int dst = edge_index[N_EDGES + e];
        int pos = g_off[dst] + atomicAdd(&g_cur[dst], 1);
        float norm = g_dinv[src] * g_dinv[dst];
        g_csr[pos] = make_int2(src, __float_as_int(norm));
    }
}

// -------------------- propagation --------------------
// one warp per node, float2 per lane (32 lanes x 2 = 64 dims).
// Edge loop unrolled x2 for MLP.
__device__ __forceinline__ float2 gather_node(const float2* __restrict__ xin,
                                              int beg, int end, int lane) {
    float2 sum = make_float2(0.0f, 0.0f);
    int e = beg;
    for (; e + 1 < end; e += 2) {
        int2 p0 = g_csr[e];
        int2 p1 = g_csr[e + 1];
        float2 v0 = xin[(size_t)p0.x * 32 + lane];
        float2 v1 = xin[(size_t)p1.x * 32 + lane];
        float w0 = __int_as_float(p0.y);
        float w1 = __int_as_float(p1.y);
        sum.x = fmaf(v0.x, w0, sum.x);
        sum.y = fmaf(v0.y, w0, sum.y);
        sum.x = fmaf(v1.x, w1, sum.x);
        sum.y = fmaf(v1.y, w1, sum.y);
    }
    if (e < end) {
        int2 p = g_csr[e];
        float2 v = xin[(size_t)p.x * 32 + lane];
        float w = __int_as_float(p.y);
        sum.x = fmaf(v.x, w, sum.x);
        sum.y = fmaf(v.y, w, sum.y);
    }
    return sum;
}

// layer 1: g_x1 = A~ * emb   (emb is a harness pointer — safe to pass)
__global__ void __launch_bounds__(256) k_prop1(const float2* __restrict__ emb) {
    int gtid = blockIdx.x * blockDim.x + threadIdx.x;
    int node = gtid >> 5;
    int lane = gtid & 31;
    if (node >= N_NODES) return;
    float2 sum = gather_node(emb, g_off[node], g_off[node + 1], lane);
    ((float2*)g_x1)[(size_t)node * 32 + lane] = sum;
}

// layer 2: g_x2 = A~ * g_x1   (globals referenced in device code only)
__global__ void __launch_bounds__(256) k_prop2() {
    int gtid = blockIdx.x * blockDim.x + threadIdx.x;
    int node = gtid >> 5;
    int lane = gtid & 31;
    if (node >= N_NODES) return;
    float2 sum = gather_node((const float2*)g_x1, g_off[node], g_off[node + 1], lane);
    ((float2*)g_x2)[(size_t)node * 32 + lane] = sum;
}

// layer 3 fused with epilogue: out = 0.25*(emb + l1 + l2 + A~*l2)
__global__ void __launch_bounds__(256) k_prop_last(const float2* __restrict__ emb,
                                                   float2* __restrict__ out) {
    int gtid = blockIdx.x * blockDim.x + threadIdx.x;
    int node = gtid >> 5;
    int lane = gtid & 31;
    if (node >= N_NODES) return;

    float2 sum = gather_node((const float2*)g_x2, g_off[node], g_off[node + 1], lane);

    size_t oi = (size_t)node * 32 + lane;
    float2 e0 = emb[oi];
    float2 a1 = ((const float2*)g_x1)[oi];
    float2 a2 = ((const float2*)g_x2)[oi];
    float2 o;
    o.x = 0.25f * (e0.x + a1.x + a2.x + sum.x);
    o.y = 0.25f * (e0.y + a1.y + a2.y + sum.y);
    out[oi] = o;
}

// -------------------- launch --------------------

extern "C" void kernel_launch(void* const* d_in, const int* in_sizes, int n_in,
                              void* d_out, int out_size) {
    const int*   edge_index = (const int*)d_in[0];     // int32 (JAX x64 disabled)
    const float* emb_weight = (const float*)d_in[1];
    float*       out        = (float*)d_out;

    const int BS = 256;
    int gn = (N_NODES + BS - 1) / BS;
    int ge = (N_EDGES + BS - 1) / BS;

    k_init_counts<<<gn, BS>>>();
    k_degree<<<ge, BS>>>(edge_index);
    k_dinv<<<gn, BS>>>();
    k_scan_blocks<<<N_SCAN_BLOCKS, SCAN_BS>>>();
    k_scan_aux<<<1, 32>>>();
    k_scan_add<<<gn, BS>>>();
    k_scatter<<<ge, BS>>>(edge_index);

    int gp = (N_NODES * 32 + BS - 1) / BS;
    k_prop1<<<gp, BS>>>((const float2*)emb_weight);              // L1
    k_prop2<<<gp, BS>>>();                                       // L2
    k_prop_last<<<gp, BS>>>((const float2*)emb_weight, (float2*)out); // L3 + epilogue
}